// round 14
// baseline (speedup 1.0000x reference)
#include <cuda_runtime.h>
#include <cuda_fp16.h>
#include <mma.h>
#include <cstdint>
using namespace nvcuda;

#define NN 16384
#define NE 8192
#define CH 256
#define NY (NN / 64)
#define S20 1048576.0f   // 2^20 exact

// ---------------- device-global scratch (allocation-free) ----------------
__device__ __align__(256) __half g_B1h [(size_t)NN * NE];   // B1 fp16 [n][e]
__device__ __align__(256) __half g_B1Th[(size_t)NE * NN];   // B1^T fp16 [e][n]
__device__ __align__(256) __half g_x0h [NN * CH];
__device__ __align__(256) __half g_W0h [CH * CH];           // [k][n] row-major
__device__ __align__(256) __half g_W1h [CH * CH];
__device__ __align__(256) __half g_Yh  [NN * CH];           // nc[n]*(x0@W0), fp16 [n][c]
__device__ __align__(256) __half g_X1h [NE * CH];           // x_1 (pre-relu) fp16
__device__ __align__(256) __half g_Zh  [NE * CH];           // ec*2^20*(x1@W1) fp16
__device__ __align__(256) float  g_acc [(size_t)NN * CH];   // shared f32 accumulator
__device__ float g_colpart[(size_t)NY * NE];                // deterministic colsum partials
__device__ float g_ec[NE], g_ecS[NE], g_nc[NN], g_d0invS[NN], g_d1inv[NE];

// ---------------- helpers ----------------
__device__ __forceinline__ uint32_t sm_u32(const void* p) {
    return (uint32_t)__cvta_generic_to_shared(p);
}
__device__ __forceinline__ void cp16(uint32_t d, const void* s) {
    asm volatile("cp.async.cg.shared.global [%0],[%1],16;" :: "r"(d), "l"(s));
}

// ---------------- prep kernels ----------------
// f32 -> fp16 convert, dual layout, deterministic per-block col partial sums.
// grid (NE/256, NN/64), 256 threads.
__global__ void __launch_bounds__(256) k_conv(const float* __restrict__ B1) {
    __shared__ __align__(16) __half sm[256][72];
    const int t = threadIdx.x;
    const int e0 = blockIdx.x * 256, n0 = blockIdx.y * 64;
    float cs = 0.f;
    for (int i = 0; i < 64; ++i) {
        size_t gi = (size_t)(n0 + i) * NE + e0 + t;
        float v = B1[gi];
        __half h = __float2half_rn(v);
        g_B1h[gi] = h;
        sm[t][i] = h;
        cs += v;
    }
    g_colpart[(size_t)blockIdx.y * NE + e0 + t] = cs;
    __syncthreads();
    const int r = t >> 3, p = t & 7;
    #pragma unroll
    for (int j = 0; j < 8; ++j) {
        int rr = r + j * 32;
        uint4 u = *(const uint4*)&sm[rr][p * 8];
        *(uint4*)&g_B1Th[(size_t)(e0 + rr) * NN + n0 + p * 8] = u;
    }
}

__global__ void k_colred() {
    int e = blockIdx.x * 256 + threadIdx.x;
    float s = 0.f;
    for (int pp = 0; pp < NY; ++pp) s += g_colpart[(size_t)pp * NE + e];
    float r = rsqrtf(s);
    float ec = r * r * r;               // card^-1.5
    g_ec[e] = ec;
    g_ecS[e] = ec * S20;
}

// per node: rowsum -> nc ; dot(B1 row, ec) -> d0invS. grid NN, 256 thr.
__global__ void __launch_bounds__(256) k_d0() {
    const int n = blockIdx.x, t = threadIdx.x;
    const __half* row = &g_B1h[(size_t)n * NE];
    float s = 0.f, sr = 0.f;
    #pragma unroll
    for (int j = 0; j < 4; ++j) {
        int base = (j * 256 + t) * 8;
        uint4 u = *(const uint4*)(row + base);
        const __half2* hp = (const __half2*)&u;
        #pragma unroll
        for (int q = 0; q < 4; ++q) {
            float2 f = __half22float2(hp[q]);
            sr += f.x + f.y;
            s += f.x * g_ec[base + 2 * q] + f.y * g_ec[base + 2 * q + 1];
        }
    }
    #pragma unroll
    for (int o = 16; o; o >>= 1) {
        s  += __shfl_xor_sync(0xffffffffu, s, o);
        sr += __shfl_xor_sync(0xffffffffu, sr, o);
    }
    __shared__ float rs[8], rr2[8];
    if ((t & 31) == 0) { rs[t >> 5] = s; rr2[t >> 5] = sr; }
    __syncthreads();
    if (t == 0) {
        float ts = 0.f, tr = 0.f;
        #pragma unroll
        for (int w = 0; w < 8; ++w) { ts += rs[w]; tr += rr2[w]; }
        g_nc[n] = rsqrtf(tr);
        g_d0invS[n] = 1.f / (S20 * ts);
    }
}

// per edge: dot(B1^T row, nc) -> d1inv. grid NE, 256 thr.
__global__ void __launch_bounds__(256) k_d1() {
    const int e = blockIdx.x, t = threadIdx.x;
    const __half* row = &g_B1Th[(size_t)e * NN];
    float s = 0.f;
    #pragma unroll
    for (int j = 0; j < 8; ++j) {
        int base = (j * 256 + t) * 8;
        uint4 u = *(const uint4*)(row + base);
        const __half2* hp = (const __half2*)&u;
        #pragma unroll
        for (int q = 0; q < 4; ++q) {
            float2 f = __half22float2(hp[q]);
            s += f.x * g_nc[base + 2 * q] + f.y * g_nc[base + 2 * q + 1];
        }
    }
    #pragma unroll
    for (int o = 16; o; o >>= 1) s += __shfl_xor_sync(0xffffffffu, s, o);
    __shared__ float red[8];
    if ((t & 31) == 0) red[t >> 5] = s;
    __syncthreads();
    if (t == 0) {
        float tot = 0.f;
        #pragma unroll
        for (int w = 0; w < 8; ++w) tot += red[w];
        g_d1inv[e] = 1.f / tot;
    }
}

__global__ void k_cvt(const float* __restrict__ x0, const float* __restrict__ W0,
                      const float* __restrict__ W1) {
    int t = blockIdx.x * 256 + threadIdx.x;
    g_x0h[t] = __float2half_rn(x0[t]);
    if (t < CH * CH) {
        g_W0h[t] = __float2half_rn(W0[t]);
        g_W1h[t] = __float2half_rn(W1[t]);
    }
}

// ---------------- small fp16 WMMA GEMM (proven): g_acc = A[Mx256] @ B[256x256]
template <int EPI>  // 0: A=x0h (M=NN), 2: A=X1h (M=NE)
__global__ void __launch_bounds__(256) k_small() {
    constexpr int K = CH;
    const __half* A = (EPI == 0) ? g_x0h : g_X1h;
    const __half* B = (EPI == 0) ? g_W0h : g_W1h;

    __shared__ __align__(32) __half As[2][2560];      // [m][k] pitch 40
    __shared__ __align__(32) __half Bs[2][32 * 264];  // [k][n] pitch 264

    const int t = threadIdx.x;
    const int m0 = blockIdx.x * 64;
    const uint32_t asb = sm_u32(&As[0][0]);
    const uint32_t bsb = sm_u32(&Bs[0][0]);

    wmma::fragment<wmma::accumulator, 16, 16, 16, float> acc[2][4];
    #pragma unroll
    for (int i = 0; i < 2; ++i)
        #pragma unroll
        for (int j = 0; j < 4; ++j) wmma::fill_fragment(acc[i][j], 0.f);

    auto load = [&](int s, int k0) {
        int m = t >> 2, kc = (t & 3) * 8;
        cp16(asb + (uint32_t)(s * 2560 + m * 40 + kc) * 2,
             A + (size_t)(m0 + m) * K + k0 + kc);
        #pragma unroll
        for (int j = 0; j < 4; ++j) {
            int lin = j * 256 + t;
            int k = lin >> 5, nc2 = (lin & 31) * 8;
            cp16(bsb + (uint32_t)(s * 32 * 264 + k * 264 + nc2) * 2,
                 B + (size_t)(k0 + k) * CH + nc2);
        }
    };

    load(0, 0);
    asm volatile("cp.async.commit_group;");
    const int wid = t >> 5, wm = wid >> 2, wn = wid & 3;

    #pragma unroll 1
    for (int kt = 0; kt < 8; ++kt) {
        const int s = kt & 1;
        if (kt + 1 < 8) load(s ^ 1, (kt + 1) * 32);
        asm volatile("cp.async.commit_group;");
        asm volatile("cp.async.wait_group 1;");
        __syncthreads();
        #pragma unroll
        for (int ks = 0; ks < 2; ++ks) {
            wmma::fragment<wmma::matrix_b, 16, 16, 16, __half, wmma::row_major> bf[4];
            #pragma unroll
            for (int nb = 0; nb < 4; ++nb)
                wmma::load_matrix_sync(bf[nb], &Bs[s][(ks * 16) * 264 + wn * 64 + nb * 16], 264);
            wmma::fragment<wmma::matrix_a, 16, 16, 16, __half, wmma::row_major> af[2];
            #pragma unroll
            for (int ma = 0; ma < 2; ++ma)
                wmma::load_matrix_sync(af[ma], &As[s][(wm * 32 + ma * 16) * 40 + ks * 16], 40);
            #pragma unroll
            for (int ma = 0; ma < 2; ++ma)
                #pragma unroll
                for (int nb = 0; nb < 4; ++nb)
                    wmma::mma_sync(acc[ma][nb], af[ma], bf[nb], acc[ma][nb]);
        }
        __syncthreads();
    }
    #pragma unroll
    for (int ma = 0; ma < 2; ++ma)
        #pragma unroll
        for (int nb = 0; nb < 4; ++nb)
            wmma::store_matrix_sync(&g_acc[(size_t)(m0 + wm * 32 + ma * 16) * CH + wn * 64 + nb * 16],
                                    acc[ma][nb], CH, wmma::mem_row_major);
}

__global__ void k_epiY() {
    int t = blockIdx.x * 256 + threadIdx.x;
    g_Yh[t] = __float2half_rn(g_acc[t] * g_nc[t >> 8]);
}
__global__ void k_epiZ() {
    int t = blockIdx.x * 256 + threadIdx.x;
    g_Zh[t] = __float2half_rn(g_acc[t] * g_ecS[t >> 8]);
}

// ---------------- big fp16 WMMA GEMM: g_acc[M,256] tile = A[MxK] @ B[Kx256] ----------------
// EPI1: A=B1Th (M=NE,K=NN), B=Yh.   EPI3: A=B1h (M=NN,K=NE), B=Zh.
#define BM 128
#define BN 128
#define BK 64
#define APITCH 72
#define BPITCH 136
#define STG_H (BM * APITCH + BK * BPITCH)   // 17920 halves per stage
#define SMEMB (2 * STG_H * 2)               // 71680 bytes

template <int EPI>
__global__ void __launch_bounds__(256, 1) k_big() {
    constexpr int K = (EPI == 1) ? NN : NE;
    constexpr int KT = K / BK;
    const __half* A = (EPI == 1) ? g_B1Th : g_B1h;
    const __half* B = (EPI == 1) ? g_Yh : g_Zh;

    extern __shared__ __align__(32) __half smh[];
    const int t = threadIdx.x, wid = t >> 5;
    const int wm = wid >> 1, wn = wid & 1;
    const int m0 = blockIdx.x * BM, nb0 = blockIdx.y * BN;

    wmma::fragment<wmma::accumulator, 16, 16, 16, float> acc[2][4];
    #pragma unroll
    for (int i = 0; i < 2; ++i)
        #pragma unroll
        for (int j = 0; j < 4; ++j) wmma::fill_fragment(acc[i][j], 0.f);

    auto load = [&](int s, int k0) {
        __half* as_ = smh + s * STG_H;
        __half* bs_ = as_ + BM * APITCH;
        const uint32_t au = sm_u32(as_), bu = sm_u32(bs_);
        #pragma unroll
        for (int j = 0; j < 4; ++j) {
            int idx = j * 256 + t;
            int row = idx >> 3, seg = idx & 7;
            cp16(au + (uint32_t)(row * APITCH + seg * 8) * 2,
                 A + (size_t)(m0 + row) * K + k0 + seg * 8);
        }
        #pragma unroll
        for (int j = 0; j < 4; ++j) {
            int idx = j * 256 + t;
            int row = idx >> 4, seg = idx & 15;
            cp16(bu + (uint32_t)(row * BPITCH + seg * 8) * 2,
                 B + (size_t)(k0 + row) * CH + nb0 + seg * 8);
        }
    };

    load(0, 0);
    asm volatile("cp.async.commit_group;");
    load(1, BK);
    asm volatile("cp.async.commit_group;");

    #pragma unroll 1
    for (int c = 0; c < KT; ++c) {
        const int s = c & 1;
        asm volatile("cp.async.wait_group 1;");
        __syncthreads();
        const __half* as_ = smh + s * STG_H;
        const __half* bs_ = as_ + BM * APITCH;
        #pragma unroll
        for (int ks = 0; ks < 4; ++ks) {
            wmma::fragment<wmma::matrix_a, 16, 16, 16, __half, wmma::row_major> af[2];
            #pragma unroll
            for (int ma = 0; ma < 2; ++ma)
                wmma::load_matrix_sync(af[ma],
                    as_ + (wm * 32 + ma * 16) * APITCH + ks * 16, APITCH);
            wmma::fragment<wmma::matrix_b, 16, 16, 16, __half, wmma::row_major> bf[4];
            #pragma unroll
            for (int nb = 0; nb < 4; ++nb)
                wmma::load_matrix_sync(bf[nb],
                    bs_ + (ks * 16) * BPITCH + wn * 64 + nb * 16, BPITCH);
            #pragma unroll
            for (int ma = 0; ma < 2; ++ma)
                #pragma unroll
                for (int nb = 0; nb < 4; ++nb)
                    wmma::mma_sync(acc[ma][nb], af[ma], bf[nb], acc[ma][nb]);
        }
        __syncthreads();
        if (c + 2 < KT) load(s, (c + 2) * BK);
        asm volatile("cp.async.commit_group;");
    }

    #pragma unroll
    for (int ma = 0; ma < 2; ++ma)
        #pragma unroll
        for (int nb = 0; nb < 4; ++nb)
            wmma::store_matrix_sync(
                &g_acc[(size_t)(m0 + wm * 32 + ma * 16) * CH + nb0 + wn * 64 + nb * 16],
                acc[ma][nb], CH, wmma::mem_row_major);
}

// ---------------- big-GEMM epilogues ----------------
__global__ void k_epi1(const float* __restrict__ bias, float* __restrict__ outF) {
    int t = blockIdx.x * 256 + threadIdx.x;
    int row = t >> 8, col = t & 255;
    float v = g_acc[t] * g_d1inv[row] + bias[col];
    g_X1h[t] = __float2half_rn(v);
    if (outF) outF[t] = fmaxf(v, 0.f);
}
__global__ void k_epi3(const float* __restrict__ bias, float* __restrict__ outF) {
    int t = blockIdx.x * 256 + threadIdx.x;
    int row = t >> 8, col = t & 255;
    outF[t] = fmaxf(g_acc[t] * g_d0invS[row] + bias[col], 0.f);
}

// ---------------- launch ----------------
extern "C" void kernel_launch(void* const* d_in, const int* in_sizes, int n_in,
                              void* d_out, int out_size) {
    const float* x0  = (const float*)d_in[0];
    const float* B1  = (const float*)d_in[1];
    const float* W0  = (const float*)d_in[2];
    const float* W1  = (const float*)d_in[3];
    const float* b01 = (const float*)d_in[4];
    const float* b10 = (const float*)d_in[5];
    float* out = (float*)d_out;
    float* out_x1 = (out_size >= NN * CH + NE * CH) ? out + (size_t)NN * CH : nullptr;

    cudaFuncSetAttribute((const void*)k_big<1>, cudaFuncAttributeMaxDynamicSharedMemorySize, SMEMB);
    cudaFuncSetAttribute((const void*)k_big<3>, cudaFuncAttributeMaxDynamicSharedMemorySize, SMEMB);

    k_conv  <<<dim3(NE / 256, NN / 64), 256>>>(B1);
    k_cvt   <<<NN * CH / 256, 256>>>(x0, W0, W1);
    k_colred<<<NE / 256, 256>>>();
    k_d0    <<<NN, 256>>>();
    k_d1    <<<NE, 256>>>();

    k_small<0><<<NN / 64, 256>>>();
    k_epiY    <<<NN * CH / 256, 256>>>();
    k_big<1>  <<<dim3(NE / BM, CH / BN), 256, SMEMB>>>();
    k_epi1    <<<NE * CH / 256, 256>>>(b01, out_x1);

    k_small<2><<<NE / 64, 256>>>();
    k_epiZ    <<<NE * CH / 256, 256>>>();
    k_big<3>  <<<dim3(NN / BM, CH / BN), 256, SMEMB>>>();
    k_epi3    <<<NN * CH / 256, 256>>>(b10, out);
}

// round 15
// speedup vs baseline: 1.1174x; 1.1174x over previous
#include <cuda_runtime.h>
#include <cuda_fp16.h>
#include <mma.h>
#include <cstdint>
using namespace nvcuda;

#define NN 16384
#define NE 8192
#define CH 256
#define NY (NN / 64)        // 256 conv row-blocks
#define ND1 32              // d1 partial row-chunks (NN/512)
#define S20 1048576.0f      // 2^20 exact

// ---------------- device-global scratch (allocation-free) ----------------
__device__ __align__(256) __half g_B1h [(size_t)NN * NE];   // B1 fp16 [n][e]
__device__ __align__(256) __half g_x0h [NN * CH];
__device__ __align__(256) __half g_W0h [CH * CH];
__device__ __align__(256) __half g_W1h [CH * CH];
__device__ __align__(256) __half g_Yh  [NN * CH];           // nc[n]*(x0@W0) fp16
__device__ __align__(256) __half g_X1h [NE * CH];           // x_1 (pre-relu) fp16
__device__ __align__(256) __half g_Zh  [NE * CH];           // ec*2^20*(x1@W1) fp16
__device__ __align__(256) float  g_acc [(size_t)NN * CH];   // small-GEMM accumulator
__device__ float g_colpart[(size_t)NY * NE];                // colsum partials
__device__ float g_d1part [(size_t)ND1 * NE];               // d1 partials
__device__ float g_ec[NE], g_ecS[NE], g_nc[NN], g_d0invS[NN], g_d1inv[NE];

// ---------------- helpers ----------------
__device__ __forceinline__ uint32_t sm_u32(const void* p) {
    return (uint32_t)__cvta_generic_to_shared(p);
}
__device__ __forceinline__ void cp16(uint32_t d, const void* s) {
    asm volatile("cp.async.cg.shared.global [%0],[%1],16;" :: "r"(d), "l"(s));
}

// ---------------- prep kernels ----------------
// f32 -> fp16 convert + deterministic col partial sums. grid (NE/256, NN/64).
__global__ void __launch_bounds__(256) k_conv(const float* __restrict__ B1) {
    const int t = threadIdx.x;
    const int e = blockIdx.x * 256 + t;
    const int n0 = blockIdx.y * 64;
    float cs = 0.f;
    #pragma unroll 4
    for (int i = 0; i < 64; ++i) {
        size_t gi = (size_t)(n0 + i) * NE + e;
        float v = B1[gi];
        g_B1h[gi] = __float2half_rn(v);
        cs += v;
    }
    g_colpart[(size_t)blockIdx.y * NE + e] = cs;
}

__global__ void k_colred() {
    int e = blockIdx.x * 256 + threadIdx.x;
    float s = 0.f;
    for (int p = 0; p < NY; ++p) s += g_colpart[(size_t)p * NE + e];
    float r = rsqrtf(s);
    float ec = r * r * r;               // card^-1.5
    g_ec[e] = ec;
    g_ecS[e] = ec * S20;
}

// per node: rowsum -> nc ; dot(B1 row, ec) -> d0invS. grid NN, 256 thr.
__global__ void __launch_bounds__(256) k_d0() {
    const int n = blockIdx.x, t = threadIdx.x;
    const __half* row = &g_B1h[(size_t)n * NE];
    float s = 0.f, sr = 0.f;
    #pragma unroll
    for (int j = 0; j < 4; ++j) {
        int base = (j * 256 + t) * 8;
        uint4 u = *(const uint4*)(row + base);
        float4 e0 = *(const float4*)&g_ec[base];
        float4 e1 = *(const float4*)&g_ec[base + 4];
        const __half2* hp = (const __half2*)&u;
        float2 f0 = __half22float2(hp[0]), f1 = __half22float2(hp[1]);
        float2 f2 = __half22float2(hp[2]), f3 = __half22float2(hp[3]);
        sr += f0.x + f0.y + f1.x + f1.y + f2.x + f2.y + f3.x + f3.y;
        s += f0.x * e0.x + f0.y * e0.y + f1.x * e0.z + f1.y * e0.w
           + f2.x * e1.x + f2.y * e1.y + f3.x * e1.z + f3.y * e1.w;
    }
    #pragma unroll
    for (int o = 16; o; o >>= 1) {
        s  += __shfl_xor_sync(0xffffffffu, s, o);
        sr += __shfl_xor_sync(0xffffffffu, sr, o);
    }
    __shared__ float rs[8], rr[8];
    if ((t & 31) == 0) { rs[t >> 5] = s; rr[t >> 5] = sr; }
    __syncthreads();
    if (t == 0) {
        float ts = 0.f, tr = 0.f;
        #pragma unroll
        for (int w = 0; w < 8; ++w) { ts += rs[w]; tr += rr[w]; }
        g_nc[n] = rsqrtf(tr);
        g_d0invS[n] = 1.f / (S20 * ts);
    }
}

// d1 partials: block (bx, by) covers e-range [bx*2048, +2048), n-range [by*512, +512).
// reads B1h row-coalesced. grid (NE/2048=4, ND1=32), 256 thr.
__global__ void __launch_bounds__(256) k_d1p() {
    __shared__ float snc[512];
    const int t = threadIdx.x;
    const int ebase = blockIdx.x * 2048 + t * 8;
    const int n0 = blockIdx.y * 512;
    snc[t] = g_nc[n0 + t];
    snc[t + 256] = g_nc[n0 + t + 256];
    __syncthreads();
    float a0 = 0.f, a1 = 0.f, a2 = 0.f, a3 = 0.f, a4 = 0.f, a5 = 0.f, a6 = 0.f, a7 = 0.f;
    #pragma unroll 4
    for (int r = 0; r < 512; ++r) {
        uint4 u = *(const uint4*)&g_B1h[(size_t)(n0 + r) * NE + ebase];
        float w = snc[r];
        const __half2* hp = (const __half2*)&u;
        float2 f0 = __half22float2(hp[0]), f1 = __half22float2(hp[1]);
        float2 f2 = __half22float2(hp[2]), f3 = __half22float2(hp[3]);
        a0 += f0.x * w; a1 += f0.y * w; a2 += f1.x * w; a3 += f1.y * w;
        a4 += f2.x * w; a5 += f2.y * w; a6 += f3.x * w; a7 += f3.y * w;
    }
    float* dst = &g_d1part[(size_t)blockIdx.y * NE + ebase];
    float4 o0 = {a0, a1, a2, a3}, o1 = {a4, a5, a6, a7};
    *(float4*)dst = o0;
    *(float4*)(dst + 4) = o1;
}

__global__ void k_d1red() {
    int e = blockIdx.x * 256 + threadIdx.x;
    float s = 0.f;
    #pragma unroll
    for (int p = 0; p < ND1; ++p) s += g_d1part[(size_t)p * NE + e];
    g_d1inv[e] = 1.f / s;
}

__global__ void k_cvt(const float* __restrict__ x0, const float* __restrict__ W0,
                      const float* __restrict__ W1) {
    int t = blockIdx.x * 256 + threadIdx.x;
    g_x0h[t] = __float2half_rn(x0[t]);
    if (t < CH * CH) {
        g_W0h[t] = __float2half_rn(W0[t]);
        g_W1h[t] = __float2half_rn(W1[t]);
    }
}

// ---------------- small fp16 WMMA GEMM (proven): g_acc = A[Mx256] @ B[256x256]
template <int EPI>  // 0: A=x0h (M=NN), 2: A=X1h (M=NE)
__global__ void __launch_bounds__(256) k_small() {
    constexpr int K = CH;
    const __half* A = (EPI == 0) ? g_x0h : g_X1h;
    const __half* B = (EPI == 0) ? g_W0h : g_W1h;

    __shared__ __align__(32) __half As[2][2560];      // [m][k] pitch 40
    __shared__ __align__(32) __half Bs[2][32 * 264];  // [k][n] pitch 264

    const int t = threadIdx.x;
    const int m0 = blockIdx.x * 64;
    const uint32_t asb = sm_u32(&As[0][0]);
    const uint32_t bsb = sm_u32(&Bs[0][0]);

    wmma::fragment<wmma::accumulator, 16, 16, 16, float> acc[2][4];
    #pragma unroll
    for (int i = 0; i < 2; ++i)
        #pragma unroll
        for (int j = 0; j < 4; ++j) wmma::fill_fragment(acc[i][j], 0.f);

    auto load = [&](int s, int k0) {
        int m = t >> 2, kc = (t & 3) * 8;
        cp16(asb + (uint32_t)(s * 2560 + m * 40 + kc) * 2,
             A + (size_t)(m0 + m) * K + k0 + kc);
        #pragma unroll
        for (int j = 0; j < 4; ++j) {
            int lin = j * 256 + t;
            int k = lin >> 5, nc2 = (lin & 31) * 8;
            cp16(bsb + (uint32_t)(s * 32 * 264 + k * 264 + nc2) * 2,
                 B + (size_t)(k0 + k) * CH + nc2);
        }
    };

    load(0, 0);
    asm volatile("cp.async.commit_group;");
    const int wid = t >> 5, wm = wid >> 2, wn = wid & 3;

    #pragma unroll 1
    for (int kt = 0; kt < 8; ++kt) {
        const int s = kt & 1;
        if (kt + 1 < 8) load(s ^ 1, (kt + 1) * 32);
        asm volatile("cp.async.commit_group;");
        asm volatile("cp.async.wait_group 1;");
        __syncthreads();
        #pragma unroll
        for (int ks = 0; ks < 2; ++ks) {
            wmma::fragment<wmma::matrix_b, 16, 16, 16, __half, wmma::row_major> bf[4];
            #pragma unroll
            for (int nb = 0; nb < 4; ++nb)
                wmma::load_matrix_sync(bf[nb], &Bs[s][(ks * 16) * 264 + wn * 64 + nb * 16], 264);
            wmma::fragment<wmma::matrix_a, 16, 16, 16, __half, wmma::row_major> af[2];
            #pragma unroll
            for (int ma = 0; ma < 2; ++ma)
                wmma::load_matrix_sync(af[ma], &As[s][(wm * 32 + ma * 16) * 40 + ks * 16], 40);
            #pragma unroll
            for (int ma = 0; ma < 2; ++ma)
                #pragma unroll
                for (int nb = 0; nb < 4; ++nb)
                    wmma::mma_sync(acc[ma][nb], af[ma], bf[nb], acc[ma][nb]);
        }
        __syncthreads();
    }
    #pragma unroll
    for (int ma = 0; ma < 2; ++ma)
        #pragma unroll
        for (int nb = 0; nb < 4; ++nb)
            wmma::store_matrix_sync(&g_acc[(size_t)(m0 + wm * 32 + ma * 16) * CH + wn * 64 + nb * 16],
                                    acc[ma][nb], CH, wmma::mem_row_major);
}

__global__ void k_epiY() {
    int t = blockIdx.x * 256 + threadIdx.x;
    g_Yh[t] = __float2half_rn(g_acc[t] * g_nc[t >> 8]);
}
__global__ void k_epiZ() {
    int t = blockIdx.x * 256 + threadIdx.x;
    g_Zh[t] = __float2half_rn(g_acc[t] * g_ecS[t >> 8]);
}

// ---------------- big fp16 WMMA GEMM + fused epilogue ----------------
// EPI1: x1 = (B1^T @ Yh)*d1inv + b01 -> X1h fp16, outF relu.  A col-major from B1h. M=NE,K=NN.
// EPI3: out = relu((B1 @ Zh)*d0invS + b10).                   A row-major from B1h. M=NN,K=NE.
#define BM 64
#define BN 128
#define BK 64
#define AP 72
#define BP 136
#define STG_H (BK * AP + BK * BP)        // 4608 + 8704 = 13312 halves / stage
#define SMEMB (2 * STG_H * 2)            // 53248 bytes

template <int EPI>
__global__ void __launch_bounds__(256, 2) k_big(const float* __restrict__ bias,
                                                float* __restrict__ outF) {
    constexpr int K = (EPI == 1) ? NN : NE;
    constexpr int KT = K / BK;
    const __half* B = (EPI == 1) ? g_Yh : g_Zh;
    const float* rsc = (EPI == 1) ? g_d1inv : g_d0invS;

    extern __shared__ __align__(32) __half smh[];
    const int t = threadIdx.x, wid = t >> 5;
    const int wm = wid >> 2, wn = wid & 3;       // 2 m-warps x 4 n-warps, warp tile 32x32
    const int m0 = blockIdx.x * BM, nb0 = blockIdx.y * BN;

    wmma::fragment<wmma::accumulator, 16, 16, 16, float> acc[2][2];
    #pragma unroll
    for (int i = 0; i < 2; ++i)
        #pragma unroll
        for (int j = 0; j < 2; ++j) wmma::fill_fragment(acc[i][j], 0.f);

    auto load = [&](int s, int k0) {
        __half* as_ = smh + s * STG_H;
        __half* bs_ = as_ + BK * AP;
        const uint32_t au = sm_u32(as_), bu = sm_u32(bs_);
        if (EPI == 1) {
            // A = B1^T: tile [k=n][m=e] from B1h rows (e-contiguous)
            #pragma unroll
            for (int j = 0; j < 2; ++j) {
                int idx = j * 256 + t;
                int k = idx >> 3, seg = idx & 7;
                cp16(au + (uint32_t)(k * AP + seg * 8) * 2,
                     g_B1h + (size_t)(k0 + k) * NE + m0 + seg * 8);
            }
        } else {
            // A = B1: tile [m=n][k=e]
            #pragma unroll
            for (int j = 0; j < 2; ++j) {
                int idx = j * 256 + t;
                int m = idx >> 3, seg = idx & 7;
                cp16(au + (uint32_t)(m * AP + seg * 8) * 2,
                     g_B1h + (size_t)(m0 + m) * NE + k0 + seg * 8);
            }
        }
        #pragma unroll
        for (int j = 0; j < 4; ++j) {
            int idx = j * 256 + t;
            int k = idx >> 4, seg = idx & 15;
            cp16(bu + (uint32_t)(k * BP + seg * 8) * 2,
                 B + (size_t)(k0 + k) * CH + nb0 + seg * 8);
        }
    };

    load(0, 0);
    asm volatile("cp.async.commit_group;");
    load(1, BK);
    asm volatile("cp.async.commit_group;");

    #pragma unroll 1
    for (int c = 0; c < KT; ++c) {
        const int s = c & 1;
        asm volatile("cp.async.wait_group 1;");
        __syncthreads();
        const __half* as_ = smh + s * STG_H;
        const __half* bs_ = as_ + BK * AP;
        #pragma unroll
        for (int ks = 0; ks < 4; ++ks) {
            wmma::fragment<wmma::matrix_b, 16, 16, 16, __half, wmma::row_major> bf[2];
            #pragma unroll
            for (int nb = 0; nb < 2; ++nb)
                wmma::load_matrix_sync(bf[nb], bs_ + (ks * 16) * BP + wn * 32 + nb * 16, BP);
            if (EPI == 1) {
                wmma::fragment<wmma::matrix_a, 16, 16, 16, __half, wmma::col_major> af[2];
                #pragma unroll
                for (int ma = 0; ma < 2; ++ma)
                    wmma::load_matrix_sync(af[ma], as_ + (ks * 16) * AP + wm * 32 + ma * 16, AP);
                #pragma unroll
                for (int ma = 0; ma < 2; ++ma)
                    #pragma unroll
                    for (int nb = 0; nb < 2; ++nb)
                        wmma::mma_sync(acc[ma][nb], af[ma], bf[nb], acc[ma][nb]);
            } else {
                wmma::fragment<wmma::matrix_a, 16, 16, 16, __half, wmma::row_major> af[2];
                #pragma unroll
                for (int ma = 0; ma < 2; ++ma)
                    wmma::load_matrix_sync(af[ma], as_ + (wm * 32 + ma * 16) * AP + ks * 16, AP);
                #pragma unroll
                for (int ma = 0; ma < 2; ++ma)
                    #pragma unroll
                    for (int nb = 0; nb < 2; ++nb)
                        wmma::mma_sync(acc[ma][nb], af[ma], bf[nb], acc[ma][nb]);
            }
        }
        __syncthreads();
        if (c + 2 < KT) load(s, (c + 2) * BK);
        asm volatile("cp.async.commit_group;");
    }

    // fused epilogue via smem bounce: stage 64x128 f32, pitch 132
    float* sf = (float*)smh;
    __syncthreads();
    #pragma unroll
    for (int ma = 0; ma < 2; ++ma)
        #pragma unroll
        for (int nb = 0; nb < 2; ++nb)
            wmma::store_matrix_sync(sf + (wm * 32 + ma * 16) * 132 + wn * 32 + nb * 16,
                                    acc[ma][nb], 132, wmma::mem_row_major);
    __syncthreads();

    const int r = t >> 2;                 // 64 rows, 4 threads/row
    const int c0 = (t & 3) * 32;          // 32 cols each
    const int grow = m0 + r;
    const float sc = rsc[grow];
    #pragma unroll
    for (int q = 0; q < 8; ++q) {
        float4 a = *(float4*)(sf + r * 132 + c0 + q * 4);
        const int gc = nb0 + c0 + q * 4;
        float4 bv = *(const float4*)&bias[gc];
        float v0 = a.x * sc + bv.x, v1 = a.y * sc + bv.y;
        float v2 = a.z * sc + bv.z, v3 = a.w * sc + bv.w;
        if (EPI == 1) {
            __half2 h0 = __floats2half2_rn(v0, v1), h1 = __floats2half2_rn(v2, v3);
            *(__half2*)&g_X1h[(size_t)grow * CH + gc] = h0;
            *(__half2*)&g_X1h[(size_t)grow * CH + gc + 2] = h1;
            if (outF) {
                float4 o = {fmaxf(v0, 0.f), fmaxf(v1, 0.f), fmaxf(v2, 0.f), fmaxf(v3, 0.f)};
                *(float4*)&outF[(size_t)grow * CH + gc] = o;
            }
        } else {
            float4 o = {fmaxf(v0, 0.f), fmaxf(v1, 0.f), fmaxf(v2, 0.f), fmaxf(v3, 0.f)};
            *(float4*)&outF[(size_t)grow * CH + gc] = o;
        }
    }
}

// ---------------- launch ----------------
extern "C" void kernel_launch(void* const* d_in, const int* in_sizes, int n_in,
                              void* d_out, int out_size) {
    const float* x0  = (const float*)d_in[0];
    const float* B1  = (const float*)d_in[1];
    const float* W0  = (const float*)d_in[2];
    const float* W1  = (const float*)d_in[3];
    const float* b01 = (const float*)d_in[4];
    const float* b10 = (const float*)d_in[5];
    float* out = (float*)d_out;
    float* out_x1 = (out_size >= NN * CH + NE * CH) ? out + (size_t)NN * CH : nullptr;

    cudaFuncSetAttribute((const void*)k_big<1>, cudaFuncAttributeMaxDynamicSharedMemorySize, SMEMB);
    cudaFuncSetAttribute((const void*)k_big<3>, cudaFuncAttributeMaxDynamicSharedMemorySize, SMEMB);

    k_conv  <<<dim3(NE / 256, NN / 64), 256>>>(B1);
    k_cvt   <<<NN * CH / 256, 256>>>(x0, W0, W1);
    k_colred<<<NE / 256, 256>>>();
    k_d0    <<<NN, 256>>>();
    k_d1p   <<<dim3(NE / 2048, ND1), 256>>>();
    k_d1red <<<NE / 256, 256>>>();

    k_small<0><<<NN / 64, 256>>>();
    k_epiY    <<<NN * CH / 256, 256>>>();
    k_big<1>  <<<dim3(NE / BM, CH / BN), 256, SMEMB>>>(b01, out_x1);

    k_small<2><<<NE / 64, 256>>>();
    k_epiZ    <<<NE * CH / 256, 256>>>();
    k_big<3>  <<<dim3(NN / BM, CH / BN), 256, SMEMB>>>(b10, out);
}

// round 16
// speedup vs baseline: 1.1872x; 1.0625x over previous
#include <cuda_runtime.h>
#include <cuda_fp16.h>
#include <mma.h>
#include <cstdint>
using namespace nvcuda;

#define NN 16384
#define NE 8192
#define CH 256
#define NY (NN / 64)        // 256 conv row-blocks
#define ND1 32              // d1 partial row-chunks (NN/512)
#define S20 1048576.0f      // 2^20 exact

// ---------------- device-global scratch (allocation-free) ----------------
__device__ __align__(256) __half g_B1h [(size_t)NN * NE];   // B1 fp16 [n][e]
__device__ __align__(256) __half g_x0h [NN * CH];
__device__ __align__(256) __half g_W0h [CH * CH];
__device__ __align__(256) __half g_W1h [CH * CH];
__device__ __align__(256) __half g_Yh  [NN * CH];           // nc[n]*(x0@W0) fp16
__device__ __align__(256) __half g_X1h [NE * CH];           // x_1 (pre-relu) fp16
__device__ __align__(256) __half g_Zh  [NE * CH];           // ec*2^20*(x1@W1) fp16
__device__ float g_colpart[(size_t)NY * NE];                // colsum partials
__device__ float g_d1part [(size_t)ND1 * NE];               // d1 partials
__device__ float g_ec[NE], g_ecS[NE], g_nc[NN], g_d0invS[NN], g_d1inv[NE];

// ---------------- helpers ----------------
__device__ __forceinline__ uint32_t sm_u32(const void* p) {
    return (uint32_t)__cvta_generic_to_shared(p);
}
__device__ __forceinline__ void cp16(uint32_t d, const void* s) {
    asm volatile("cp.async.cg.shared.global [%0],[%1],16;" :: "r"(d), "l"(s));
}

// ---------------- prep kernels ----------------
// f32 -> fp16 convert + deterministic col partial sums. grid (NE/256, NN/64).
__global__ void __launch_bounds__(256) k_conv(const float* __restrict__ B1) {
    const int t = threadIdx.x;
    const int e = blockIdx.x * 256 + t;
    const int n0 = blockIdx.y * 64;
    float cs = 0.f;
    #pragma unroll 4
    for (int i = 0; i < 64; ++i) {
        size_t gi = (size_t)(n0 + i) * NE + e;
        float v = B1[gi];
        g_B1h[gi] = __float2half_rn(v);
        cs += v;
    }
    g_colpart[(size_t)blockIdx.y * NE + e] = cs;
}

__global__ void k_colred() {
    int e = blockIdx.x * 256 + threadIdx.x;
    float s = 0.f;
    for (int p = 0; p < NY; ++p) s += g_colpart[(size_t)p * NE + e];
    float r = rsqrtf(s);
    float ec = r * r * r;               // card^-1.5
    g_ec[e] = ec;
    g_ecS[e] = ec * S20;
}

// per node: rowsum -> nc ; dot(B1 row, ec) -> d0invS. grid NN, 256 thr.
__global__ void __launch_bounds__(256) k_d0() {
    const int n = blockIdx.x, t = threadIdx.x;
    const __half* row = &g_B1h[(size_t)n * NE];
    float s = 0.f, sr = 0.f;
    #pragma unroll
    for (int j = 0; j < 4; ++j) {
        int base = (j * 256 + t) * 8;
        uint4 u = *(const uint4*)(row + base);
        float4 e0 = *(const float4*)&g_ec[base];
        float4 e1 = *(const float4*)&g_ec[base + 4];
        const __half2* hp = (const __half2*)&u;
        float2 f0 = __half22float2(hp[0]), f1 = __half22float2(hp[1]);
        float2 f2 = __half22float2(hp[2]), f3 = __half22float2(hp[3]);
        sr += f0.x + f0.y + f1.x + f1.y + f2.x + f2.y + f3.x + f3.y;
        s += f0.x * e0.x + f0.y * e0.y + f1.x * e0.z + f1.y * e0.w
           + f2.x * e1.x + f2.y * e1.y + f3.x * e1.z + f3.y * e1.w;
    }
    #pragma unroll
    for (int o = 16; o; o >>= 1) {
        s  += __shfl_xor_sync(0xffffffffu, s, o);
        sr += __shfl_xor_sync(0xffffffffu, sr, o);
    }
    __shared__ float rs[8], rr[8];
    if ((t & 31) == 0) { rs[t >> 5] = s; rr[t >> 5] = sr; }
    __syncthreads();
    if (t == 0) {
        float ts = 0.f, tr = 0.f;
        #pragma unroll
        for (int w = 0; w < 8; ++w) { ts += rs[w]; tr += rr[w]; }
        g_nc[n] = rsqrtf(tr);
        g_d0invS[n] = 1.f / (S20 * ts);
    }
}

// d1 partials: block (bx, by) covers e-range [bx*2048), n-range [by*512).
__global__ void __launch_bounds__(256) k_d1p() {
    __shared__ float snc[512];
    const int t = threadIdx.x;
    const int ebase = blockIdx.x * 2048 + t * 8;
    const int n0 = blockIdx.y * 512;
    snc[t] = g_nc[n0 + t];
    snc[t + 256] = g_nc[n0 + t + 256];
    __syncthreads();
    float a0 = 0.f, a1 = 0.f, a2 = 0.f, a3 = 0.f, a4 = 0.f, a5 = 0.f, a6 = 0.f, a7 = 0.f;
    #pragma unroll 4
    for (int r = 0; r < 512; ++r) {
        uint4 u = *(const uint4*)&g_B1h[(size_t)(n0 + r) * NE + ebase];
        float w = snc[r];
        const __half2* hp = (const __half2*)&u;
        float2 f0 = __half22float2(hp[0]), f1 = __half22float2(hp[1]);
        float2 f2 = __half22float2(hp[2]), f3 = __half22float2(hp[3]);
        a0 += f0.x * w; a1 += f0.y * w; a2 += f1.x * w; a3 += f1.y * w;
        a4 += f2.x * w; a5 += f2.y * w; a6 += f3.x * w; a7 += f3.y * w;
    }
    float* dst = &g_d1part[(size_t)blockIdx.y * NE + ebase];
    float4 o0 = {a0, a1, a2, a3}, o1 = {a4, a5, a6, a7};
    *(float4*)dst = o0;
    *(float4*)(dst + 4) = o1;
}

__global__ void k_d1red() {
    int e = blockIdx.x * 256 + threadIdx.x;
    float s = 0.f;
    #pragma unroll
    for (int p = 0; p < ND1; ++p) s += g_d1part[(size_t)p * NE + e];
    g_d1inv[e] = 1.f / s;
}

__global__ void k_cvt(const float* __restrict__ x0, const float* __restrict__ W0,
                      const float* __restrict__ W1) {
    int t = blockIdx.x * 256 + threadIdx.x;
    g_x0h[t] = __float2half_rn(x0[t]);
    if (t < CH * CH) {
        g_W0h[t] = __float2half_rn(W0[t]);
        g_W1h[t] = __float2half_rn(W1[t]);
    }
}

// ---------------- small fp16 WMMA GEMM with fused scale->fp16 epilogue ----------------
// EPI0: g_Yh = fp16( nc[m]  * (x0h @ W0h) ), M=NN
// EPI2: g_Zh = fp16( ecS[m] * (X1h @ W1h) ), M=NE
template <int EPI>
__global__ void __launch_bounds__(256) k_small() {
    constexpr int K = CH;
    const __half* A = (EPI == 0) ? g_x0h : g_X1h;
    const __half* B = (EPI == 0) ? g_W0h : g_W1h;
    const float* rsc = (EPI == 0) ? g_nc : g_ecS;
    __half* OUT = (EPI == 0) ? g_Yh : g_Zh;

    __shared__ __align__(32) __half As[2][2560];      // [m][k] pitch 40
    __shared__ __align__(32) __half Bs[2][32 * 264];  // [k][n] pitch 264

    const int t = threadIdx.x;
    const int m0 = blockIdx.x * 64;
    const uint32_t asb = sm_u32(&As[0][0]);
    const uint32_t bsb = sm_u32(&Bs[0][0]);

    wmma::fragment<wmma::accumulator, 16, 16, 16, float> acc[2][4];
    #pragma unroll
    for (int i = 0; i < 2; ++i)
        #pragma unroll
        for (int j = 0; j < 4; ++j) wmma::fill_fragment(acc[i][j], 0.f);

    auto load = [&](int s, int k0) {
        int m = t >> 2, kc = (t & 3) * 8;
        cp16(asb + (uint32_t)(s * 2560 + m * 40 + kc) * 2,
             A + (size_t)(m0 + m) * K + k0 + kc);
        #pragma unroll
        for (int j = 0; j < 4; ++j) {
            int lin = j * 256 + t;
            int k = lin >> 5, nc2 = (lin & 31) * 8;
            cp16(bsb + (uint32_t)(s * 32 * 264 + k * 264 + nc2) * 2,
                 B + (size_t)(k0 + k) * CH + nc2);
        }
    };

    load(0, 0);
    asm volatile("cp.async.commit_group;");
    const int wid = t >> 5, wm = wid >> 2, wn = wid & 3;
    const int lane = t & 31;

    #pragma unroll 1
    for (int kt = 0; kt < 8; ++kt) {
        const int s = kt & 1;
        if (kt + 1 < 8) load(s ^ 1, (kt + 1) * 32);
        asm volatile("cp.async.commit_group;");
        asm volatile("cp.async.wait_group 1;");
        __syncthreads();
        #pragma unroll
        for (int ks = 0; ks < 2; ++ks) {
            wmma::fragment<wmma::matrix_b, 16, 16, 16, __half, wmma::row_major> bf[4];
            #pragma unroll
            for (int nb = 0; nb < 4; ++nb)
                wmma::load_matrix_sync(bf[nb], &Bs[s][(ks * 16) * 264 + wn * 64 + nb * 16], 264);
            wmma::fragment<wmma::matrix_a, 16, 16, 16, __half, wmma::row_major> af[2];
            #pragma unroll
            for (int ma = 0; ma < 2; ++ma)
                wmma::load_matrix_sync(af[ma], &As[s][(wm * 32 + ma * 16) * 40 + ks * 16], 40);
            #pragma unroll
            for (int ma = 0; ma < 2; ++ma)
                #pragma unroll
                for (int nb = 0; nb < 4; ++nb)
                    wmma::mma_sync(acc[ma][nb], af[ma], bf[nb], acc[ma][nb]);
        }
        __syncthreads();
    }

    // fused epilogue: per-warp smem bounce (reuse As region), scale + fp16 store
    __syncthreads();
    float* scr = (float*)&As[0][0] + wid * 320;   // 16x16 tile, pitch 20
    const int erow = lane >> 1, ecl = (lane & 1) * 8;
    #pragma unroll
    for (int ma = 0; ma < 2; ++ma)
        #pragma unroll
        for (int nb = 0; nb < 4; ++nb) {
            wmma::store_matrix_sync(scr, acc[ma][nb], 20, wmma::mem_row_major);
            __syncwarp();
            const int grow = m0 + wm * 32 + ma * 16 + erow;
            const float sc = rsc[grow];
            const int gcol = wn * 64 + nb * 16 + ecl;
            __half hv[8];
            #pragma unroll
            for (int j = 0; j < 8; ++j)
                hv[j] = __float2half_rn(scr[erow * 20 + ecl + j] * sc);
            *(uint4*)&OUT[(size_t)grow * CH + gcol] = *(uint4*)hv;
            __syncwarp();
        }
}

// ---------------- big fp16 WMMA GEMM, 3-stage single-sync + fused epilogue ----------------
// EPI1: x1 = (B1^T @ Yh)*d1inv + b01 -> X1h fp16, outF relu.  A col-major from B1h. M=NE,K=NN.
// EPI3: out = relu((B1 @ Zh)*d0invS + b10).                   A row-major from B1h. M=NN,K=NE.
#define BM 64
#define BN 128
#define BK 64
#define AP 72
#define BP 136
#define STG_H (BK * AP + BK * BP)        // 13312 halves / stage
#define SMEMB (3 * STG_H * 2)            // 79872 bytes

template <int EPI>
__global__ void __launch_bounds__(256, 2) k_big(const float* __restrict__ bias,
                                                float* __restrict__ outF) {
    constexpr int K = (EPI == 1) ? NN : NE;
    constexpr int KT = K / BK;
    const __half* B = (EPI == 1) ? g_Yh : g_Zh;
    const float* rsc = (EPI == 1) ? g_d1inv : g_d0invS;

    extern __shared__ __align__(32) __half smh[];
    const int t = threadIdx.x, wid = t >> 5;
    const int wm = wid >> 2, wn = wid & 3;       // 2 m-warps x 4 n-warps, warp tile 32x32
    const int m0 = blockIdx.x * BM, nb0 = blockIdx.y * BN;

    wmma::fragment<wmma::accumulator, 16, 16, 16, float> acc[2][2];
    #pragma unroll
    for (int i = 0; i < 2; ++i)
        #pragma unroll
        for (int j = 0; j < 2; ++j) wmma::fill_fragment(acc[i][j], 0.f);

    auto load = [&](int s, int k0) {
        __half* as_ = smh + s * STG_H;
        __half* bs_ = as_ + BK * AP;
        const uint32_t au = sm_u32(as_), bu = sm_u32(bs_);
        if (EPI == 1) {
            #pragma unroll
            for (int j = 0; j < 2; ++j) {
                int idx = j * 256 + t;
                int k = idx >> 3, seg = idx & 7;
                cp16(au + (uint32_t)(k * AP + seg * 8) * 2,
                     g_B1h + (size_t)(k0 + k) * NE + m0 + seg * 8);
            }
        } else {
            #pragma unroll
            for (int j = 0; j < 2; ++j) {
                int idx = j * 256 + t;
                int m = idx >> 3, seg = idx & 7;
                cp16(au + (uint32_t)(m * AP + seg * 8) * 2,
                     g_B1h + (size_t)(m0 + m) * NE + k0 + seg * 8);
            }
        }
        #pragma unroll
        for (int j = 0; j < 4; ++j) {
            int idx = j * 256 + t;
            int k = idx >> 4, seg = idx & 15;
            cp16(bu + (uint32_t)(k * BP + seg * 8) * 2,
                 B + (size_t)(k0 + k) * CH + nb0 + seg * 8);
        }
    };

    load(0, 0);
    asm volatile("cp.async.commit_group;");
    load(1, BK);
    asm volatile("cp.async.commit_group;");

    #pragma unroll 1
    for (int c = 0; c < KT; ++c) {
        const int s = c % 3;
        asm volatile("cp.async.wait_group 1;");
        __syncthreads();
        if (c + 2 < KT) load((c + 2) % 3, (c + 2) * BK);
        asm volatile("cp.async.commit_group;");
        const __half* as_ = smh + s * STG_H;
        const __half* bs_ = as_ + BK * AP;
        #pragma unroll
        for (int ks = 0; ks < 4; ++ks) {
            wmma::fragment<wmma::matrix_b, 16, 16, 16, __half, wmma::row_major> bf[2];
            #pragma unroll
            for (int nb = 0; nb < 2; ++nb)
                wmma::load_matrix_sync(bf[nb], bs_ + (ks * 16) * BP + wn * 32 + nb * 16, BP);
            if (EPI == 1) {
                wmma::fragment<wmma::matrix_a, 16, 16, 16, __half, wmma::col_major> af[2];
                #pragma unroll
                for (int ma = 0; ma < 2; ++ma)
                    wmma::load_matrix_sync(af[ma], as_ + (ks * 16) * AP + wm * 32 + ma * 16, AP);
                #pragma unroll
                for (int ma = 0; ma < 2; ++ma)
                    #pragma unroll
                    for (int nb = 0; nb < 2; ++nb)
                        wmma::mma_sync(acc[ma][nb], af[ma], bf[nb], acc[ma][nb]);
            } else {
                wmma::fragment<wmma::matrix_a, 16, 16, 16, __half, wmma::row_major> af[2];
                #pragma unroll
                for (int ma = 0; ma < 2; ++ma)
                    wmma::load_matrix_sync(af[ma], as_ + (wm * 32 + ma * 16) * AP + ks * 16, AP);
                #pragma unroll
                for (int ma = 0; ma < 2; ++ma)
                    #pragma unroll
                    for (int nb = 0; nb < 2; ++nb)
                        wmma::mma_sync(acc[ma][nb], af[ma], bf[nb], acc[ma][nb]);
            }
        }
    }

    // fused epilogue via smem bounce: 64x128 f32, pitch 132
    asm volatile("cp.async.wait_group 0;");
    __syncthreads();
    float* sf = (float*)smh;
    #pragma unroll
    for (int ma = 0; ma < 2; ++ma)
        #pragma unroll
        for (int nb = 0; nb < 2; ++nb)
            wmma::store_matrix_sync(sf + (wm * 32 + ma * 16) * 132 + wn * 32 + nb * 16,
                                    acc[ma][nb], 132, wmma::mem_row_major);
    __syncthreads();

    const int r = t >> 2;
    const int c0 = (t & 3) * 32;
    const int grow = m0 + r;
    const float sc = rsc[grow];
    #pragma unroll
    for (int q = 0; q < 8; ++q) {
        float4 a = *(float4*)(sf + r * 132 + c0 + q * 4);
        const int gc = nb0 + c0 + q * 4;
        float4 bv = *(const float4*)&bias[gc];
        float v0 = a.x * sc + bv.x, v1 = a.y * sc + bv.y;
        float v2 = a.z * sc + bv.z, v3 = a.w * sc + bv.w;
        if (EPI == 1) {
            __half2 h0 = __floats2half2_rn(v0, v1), h1 = __floats2half2_rn(v2, v3);
            *(__half2*)&g_X1h[(size_t)grow * CH + gc] = h0;
            *(__half2*)&g_X1h[(size_t)grow * CH + gc + 2] = h1;
            if (outF) {
                float4 o = {fmaxf(v0, 0.f), fmaxf(v1, 0.f), fmaxf(v2, 0.f), fmaxf(v3, 0.f)};
                *(float4*)&outF[(size_t)grow * CH + gc] = o;
            }
        } else {
            float4 o = {fmaxf(v0, 0.f), fmaxf(v1, 0.f), fmaxf(v2, 0.f), fmaxf(v3, 0.f)};
            *(float4*)&outF[(size_t)grow * CH + gc] = o;
        }
    }
}

// ---------------- launch ----------------
extern "C" void kernel_launch(void* const* d_in, const int* in_sizes, int n_in,
                              void* d_out, int out_size) {
    const float* x0  = (const float*)d_in[0];
    const float* B1  = (const float*)d_in[1];
    const float* W0  = (const float*)d_in[2];
    const float* W1  = (const float*)d_in[3];
    const float* b01 = (const float*)d_in[4];
    const float* b10 = (const float*)d_in[5];
    float* out = (float*)d_out;
    float* out_x1 = (out_size >= NN * CH + NE * CH) ? out + (size_t)NN * CH : nullptr;

    cudaFuncSetAttribute((const void*)k_big<1>, cudaFuncAttributeMaxDynamicSharedMemorySize, SMEMB);
    cudaFuncSetAttribute((const void*)k_big<3>, cudaFuncAttributeMaxDynamicSharedMemorySize, SMEMB);

    k_conv  <<<dim3(NE / 256, NN / 64), 256>>>(B1);
    k_cvt   <<<NN * CH / 256, 256>>>(x0, W0, W1);
    k_colred<<<NE / 256, 256>>>();
    k_d0    <<<NN, 256>>>();
    k_d1p   <<<dim3(NE / 2048, ND1), 256>>>();
    k_d1red <<<NE / 256, 256>>>();

    k_small<0><<<NN / 64, 256>>>();
    k_big<1>  <<<dim3(NE / BM, CH / BN), 256, SMEMB>>>(b01, out_x1);

    k_small<2><<<NE / 64, 256>>>();
    k_big<3>  <<<dim3(NN / BM, CH / BN), 256, SMEMB>>>(b10, out);
}